// round 16
// baseline (speedup 1.0000x reference)
#include <cuda_runtime.h>
#include <cuda_fp16.h>
#include <cuda_fp8.h>
#include <cstdint>

// Problem shapes (fixed by the dataset)
#define M_FULL  16384
#define N_DIM   4096
#define K_DIM   4096
#define NPREP   148                   // prep CTAs = arrivals per segment
#define NSEG    4                     // K segments of 1024

// Scratch (allocation-free rule: __device__ globals)
__device__ __half g_A16[(size_t)(M_FULL / 2) * K_DIM];  // fp16 Asum [M][K]
__device__ __half g_B16[(size_t)K_DIM * N_DIM];          // fp16 B^T [N][K]
__device__ int    g_seg_done[NSEG];                      // per-segment arrival counters

// ---------------------------------------------------------------------------
// fp8 helpers
// ---------------------------------------------------------------------------
__device__ __forceinline__ float fp8_round(float x) {
    __nv_fp8_storage_t s = __nv_cvt_float_to_fp8(x, __NV_SATFINITE, __NV_E4M3);
    __half_raw hr = __nv_cvt_fp8_to_halfraw(s, __NV_E4M3);
    return __half2float(__half(hr));
}
__device__ __forceinline__ __half fp8_to_half(float x) {
    __nv_fp8_storage_t s = __nv_cvt_float_to_fp8(x, __NV_SATFINITE, __NV_E4M3);
    __half_raw hr = __nv_cvt_fp8_to_halfraw(s, __NV_E4M3);  // e4m3 exact in fp16
    return __half(hr);
}

// ---------------------------------------------------------------------------
// Segmented prep kernel (148 CTAs x 128 threads, runs CONCURRENTLY with GEMM):
// for each K-segment s (1024 cols): reduce+quantize A stripe, transpose+quantize
// W stripe, then arrive on g_seg_done[s].
// ---------------------------------------------------------------------------
__global__ __launch_bounds__(128)
void prep_kernel(const float* __restrict__ A, const float* __restrict__ W,
                 int M_out, int world) {
    __shared__ float t[128][33];      // 16.9 KB static (co-resident w/ GEMM's 192K)
    const int tid = threadIdx.x;
    const int bid = blockIdx.x;
    const float4* A4 = (const float4*)A;
    const float4* W4 = (const float4*)W;

    for (int s = 0; s < NSEG; s++) {
        // ---- A stripe: Asum[:, s*1024 : +1024] -> fp16 ----
        const int Q = M_out * 256;            // quads in stripe
        for (int i = bid * 128 + tid; i < Q; i += NPREP * 128) {
            int r = i >> 8, c4 = i & 255;
            float4 acc = make_float4(0.f, 0.f, 0.f, 0.f);
            for (int w = 0; w < world; w++) {
                float4 v = A4[((size_t)(w * M_out + r)) * 1024 + s * 256 + c4];
                acc.x += fp8_round(v.x);
                acc.y += fp8_round(v.y);
                acc.z += fp8_round(v.z);
                acc.w += fp8_round(v.w);
            }
            size_t q = (size_t)r * 1024 + s * 256 + c4;
            ((__half2*)g_A16)[q * 2 + 0] = __floats2half2_rn(acc.x, acc.y);
            ((__half2*)g_A16)[q * 2 + 1] = __floats2half2_rn(acc.z, acc.w);
        }

        // ---- B stripe: W[s*1024:+1024, :] -> B^T[:, s*1024:+1024] fp16 ----
        // tiles of 128(K) x 32(N): 8 x 128 = 1024 tiles per segment
        for (int q = bid; q < 1024; q += NPREP) {
            int k0 = s * 1024 + (q >> 7) * 128;
            int n0 = (q & 127) * 32;
            __syncthreads();
            // load 128x32 f32 (1024 float4, 8 per thread, MLP 8)
#pragma unroll
            for (int i = 0; i < 8; i++) {
                int idx = tid + i * 128;
                int kk = idx >> 3, q4 = idx & 7;
                float4 v = W4[(size_t)(k0 + kk) * 1024 + (n0 >> 2) + q4];
                t[kk][q4 * 4 + 0] = v.x;
                t[kk][q4 * 4 + 1] = v.y;
                t[kk][q4 * 4 + 2] = v.z;
                t[kk][q4 * 4 + 3] = v.w;
            }
            __syncthreads();
            // write: thread handles (n = tid>>2, kgroup = (tid&3)*32): 64B run
            {
                int n  = tid >> 2;
                int kg = (tid & 3) * 32;
                __half2 buf[16];
#pragma unroll
                for (int j = 0; j < 16; j++)
                    buf[j] = __halves2half2(fp8_to_half(t[kg + 2 * j][n]),
                                            fp8_to_half(t[kg + 2 * j + 1][n]));
                uint4* dst = (uint4*)&g_B16[(size_t)(n0 + n) * K_DIM + k0 + kg];
#pragma unroll
                for (int j = 0; j < 4; j++) dst[j] = ((uint4*)buf)[j];
            }
        }

        // ---- segment arrival ----
        __syncthreads();
        if (tid == 0) {
            __threadfence();
            atomicAdd(&g_seg_done[s], 1);
        }
    }
}

// ---------------------------------------------------------------------------
// PTX helpers (sm_80-era instructions; valid on compute_103)
// ---------------------------------------------------------------------------
__device__ __forceinline__ uint32_t smem_u32(const void* p) {
    uint32_t a;
    asm("{ .reg .u64 t; cvta.to.shared.u64 t, %1; cvt.u32.u64 %0, t; }" : "=r"(a) : "l"(p));
    return a;
}
__device__ __forceinline__ void ldsm_x4(uint32_t& r0, uint32_t& r1, uint32_t& r2, uint32_t& r3,
                                        uint32_t addr) {
    asm volatile("ldmatrix.sync.aligned.m8n8.x4.shared.b16 {%0,%1,%2,%3}, [%4];"
                 : "=r"(r0), "=r"(r1), "=r"(r2), "=r"(r3) : "r"(addr));
}
__device__ __forceinline__ void mma_16816(float* c, const uint32_t* a, uint32_t b0, uint32_t b1) {
    asm volatile("mma.sync.aligned.m16n8k16.row.col.f32.f16.f16.f32 "
                 "{%0,%1,%2,%3}, {%4,%5,%6,%7}, {%8,%9}, {%0,%1,%2,%3};"
                 : "+f"(c[0]), "+f"(c[1]), "+f"(c[2]), "+f"(c[3])
                 : "r"(a[0]), "r"(a[1]), "r"(a[2]), "r"(a[3]), "r"(b0), "r"(b1));
}
__device__ __forceinline__ void cp16(uint32_t smem, const void* g) {
    asm volatile("cp.async.cg.shared.global [%0], [%1], 16;" :: "r"(smem), "l"(g) : "memory");
}
#define CP_COMMIT() asm volatile("cp.async.commit_group;" ::: "memory")
#define CP_WAIT(n)  asm volatile("cp.async.wait_group %0;" :: "n"(n) : "memory")

// ---------------------------------------------------------------------------
// GEMM (R12-proven config): 128x256 CTA tile, 8 warps (64x64 warp tile),
// BK=64, 4-stage cp.async ring, reg double-buffered frags, + segment gating.
// ---------------------------------------------------------------------------
#define BM 128
#define BN 256
#define BKH 64
#define STAGES 4
#define ROWB 128
#define A_STAGE (BM * ROWB)
#define B_STAGE (BN * ROWB)
#define STAGE_BYTES (A_STAGE + B_STAGE)
#define GEMM_SMEM (STAGES * STAGE_BYTES)   // 192 KB

__device__ __forceinline__ uint32_t sw_off(int row, int chunk) {
    return (uint32_t)(row * ROWB + ((chunk ^ (row & 7)) << 4));
}

__global__ __launch_bounds__(256)
void gemm_mma_kernel(const float* __restrict__ scale_b, float* __restrict__ out) {
    extern __shared__ char sm[];
    const uint32_t sbase = smem_u32(sm);

    const int tid  = threadIdx.x;
    const int lane = tid & 31;
    const int warp = tid >> 5;
    const int wm   = warp & 1;
    const int wn   = warp >> 1;
    const int bm = blockIdx.y * BM;
    const int bn = blockIdx.x * BN;

    const __half* Ag = g_A16 + (size_t)bm * K_DIM;
    const __half* Bg = g_B16 + (size_t)bn * K_DIM;

    const int crow = tid >> 3;
    const int cchk = tid & 7;

    float acc[4][8][4] = {};

    const int KITER = K_DIM / BKH;    // 64
    const int arow = wm * 64 + (lane & 15);
    const int brow = wn * 64 + (lane & 15);
    const int chsel = lane >> 4;

    // Wait for segment 0 (prologue covers chunks 0..2, all in seg 0)
    if (tid == 0) {
        while (((volatile int*)g_seg_done)[0] < NPREP) { }
        __threadfence();
    }
    __syncthreads();

    // Prologue: fill stages 0..STAGES-2
#pragma unroll
    for (int s = 0; s < STAGES - 1; s++) {
        const __half* ga = Ag + (size_t)s * BKH + cchk * 8;
        const __half* gb = Bg + (size_t)s * BKH + cchk * 8;
        uint32_t as = sbase + s * STAGE_BYTES;
        uint32_t bs = as + A_STAGE;
#pragma unroll
        for (int i = 0; i < 4; i++)
            cp16(as + sw_off(crow + i * 32, cchk), ga + (size_t)(crow + i * 32) * K_DIM);
#pragma unroll
        for (int i = 0; i < 8; i++)
            cp16(bs + sw_off(crow + i * 32, cchk), gb + (size_t)(crow + i * 32) * K_DIM);
        CP_COMMIT();
    }

    uint32_t af[2][4][4];
    uint32_t bf[2][4][4];
    int pseg = 0;                     // last segment known ready (tid0's state)

    for (int it = 0; it < KITER; it++) {
        CP_WAIT(STAGES - 2);

        const int nk = it + STAGES - 1;
        const bool do_ld = (nk < KITER);

        // Gate the upcoming stage's loads on its K-segment being prepped
        if (tid == 0 && do_ld) {
            int sg = nk >> 4;         // 16 chunks per 1024-col segment
            if (sg > pseg) {
                while (((volatile int*)g_seg_done)[sg] < NPREP) { }
                __threadfence();
                pseg = sg;
            }
        }
        __syncthreads();

        const uint32_t As = sbase + (it % STAGES) * STAGE_BYTES;
        const uint32_t Bs = As + A_STAGE;
        const __half* ga = Ag + (size_t)nk * BKH + cchk * 8;
        const __half* gb = Bg + (size_t)nk * BKH + cchk * 8;
        const uint32_t nas = sbase + (nk % STAGES) * STAGE_BYTES;
        const uint32_t nbs = nas + A_STAGE;

        // Preload ks=0 fragments into buffer 0
        {
            const int ch = chsel;
#pragma unroll
            for (int mi = 0; mi < 4; mi++)
                ldsm_x4(af[0][mi][0], af[0][mi][1], af[0][mi][2], af[0][mi][3],
                        As + sw_off(arow + mi * 16, ch));
#pragma unroll
            for (int nj = 0; nj < 4; nj++)
                ldsm_x4(bf[0][nj][0], bf[0][nj][1], bf[0][nj][2], bf[0][nj][3],
                        Bs + sw_off(brow + nj * 16, ch));
        }

#pragma unroll
        for (int ks = 0; ks < 4; ks++) {
            const int cur = ks & 1;
            const int nxt = cur ^ 1;

            if (ks < 3) {
                const int ch = (ks + 1) * 2 + chsel;
#pragma unroll
                for (int mi = 0; mi < 4; mi++)
                    ldsm_x4(af[nxt][mi][0], af[nxt][mi][1], af[nxt][mi][2], af[nxt][mi][3],
                            As + sw_off(arow + mi * 16, ch));
#pragma unroll
                for (int nj = 0; nj < 4; nj++)
                    ldsm_x4(bf[nxt][nj][0], bf[nxt][nj][1], bf[nxt][nj][2], bf[nxt][nj][3],
                            Bs + sw_off(brow + nj * 16, ch));
            }

            if (do_ld) {
                int r = crow + ks * 32;
                cp16(nas + sw_off(r, cchk), ga + (size_t)r * K_DIM);
                int r0 = crow + (ks * 2) * 32;
                int r1 = crow + (ks * 2 + 1) * 32;
                cp16(nbs + sw_off(r0, cchk), gb + (size_t)r0 * K_DIM);
                cp16(nbs + sw_off(r1, cchk), gb + (size_t)r1 * K_DIM);
            }
            if (ks == 3) CP_COMMIT();

#pragma unroll
            for (int mi = 0; mi < 4; mi++)
#pragma unroll
                for (int n8 = 0; n8 < 8; n8++) {
                    int nj = n8 >> 1, hi = n8 & 1;
                    mma_16816(acc[mi][n8], af[cur][mi], bf[cur][nj][hi], bf[cur][nj][hi + 2]);
                }
        }
    }

    // Fused epilogue: scale_b + fp16 quantize, store fp32
#pragma unroll
    for (int mi = 0; mi < 4; mi++) {
#pragma unroll
        for (int n8 = 0; n8 < 8; n8++) {
            const float* c = acc[mi][n8];
            int row = bm + wm * 64 + mi * 16 + (lane >> 2);
            int col = bn + wn * 64 + n8 * 8 + (lane & 3) * 2;
            float2 s0 = *(const float2*)&scale_b[col];
            float2 v0;
            v0.x = __half2float(__float2half(c[0] * s0.x));
            v0.y = __half2float(__float2half(c[1] * s0.y));
            *(float2*)&out[(size_t)row * N_DIM + col] = v0;
            float2 v1;
            v1.x = __half2float(__float2half(c[2] * s0.x));
            v1.y = __half2float(__float2half(c[3] * s0.y));
            *(float2*)&out[(size_t)(row + 8) * N_DIM + col] = v1;
        }
    }
}

// ---------------------------------------------------------------------------
// Host: fork-join capture — prep on side stream CONCURRENT with GEMM.
// ---------------------------------------------------------------------------
extern "C" void kernel_launch(void* const* d_in, const int* in_sizes, int n_in,
                              void* d_out, int out_size) {
    const float* input = nullptr; const float* weight = nullptr; const float* scale_b = nullptr;
    long long input_elems = 0;
    for (int i = 0; i < n_in; i++) {
        long long sz = in_sizes[i];
        if (sz == (long long)K_DIM * N_DIM && !weight)      weight = (const float*)d_in[i];
        else if (sz == N_DIM && !scale_b)                   scale_b = (const float*)d_in[i];
        else if (sz > (long long)K_DIM * N_DIM)             { input = (const float*)d_in[i]; input_elems = sz; }
    }
    float* out = (float*)d_out;   // harness output buffer is FLOAT32

    long long M_full   = input_elems / K_DIM;
    long long out_rows = (long long)out_size / N_DIM;
    int world = (int)(M_full / (out_rows > 0 ? out_rows : M_full));
    if (world < 1) world = 1;
    int M_out = (int)(M_full / world);

    void* flags = nullptr;
    cudaGetSymbolAddress(&flags, g_seg_done);

    cudaStream_t s2;
    cudaEvent_t e1, e2;
    cudaStreamCreateWithFlags(&s2, cudaStreamNonBlocking);
    cudaEventCreateWithFlags(&e1, cudaEventDisableTiming);
    cudaEventCreateWithFlags(&e2, cudaEventDisableTiming);

    cudaFuncSetAttribute(gemm_mma_kernel, cudaFuncAttributeMaxDynamicSharedMemorySize,
                         GEMM_SMEM);

    // 1. reset segment flags (ordered before BOTH kernels)
    cudaMemsetAsync(flags, 0, sizeof(int) * NSEG, 0);
    // 2. fork: prep on s2
    cudaEventRecord(e1, 0);
    cudaStreamWaitEvent(s2, e1, 0);
    prep_kernel<<<NPREP, 128, 0, s2>>>(input, weight, M_out, world);
    cudaEventRecord(e2, s2);
    // 3. GEMM on main stream — concurrent with prep, gated by segment flags
    dim3 grid(N_DIM / BN, M_out / BM);
    gemm_mma_kernel<<<grid, 256, GEMM_SMEM>>>(scale_b, out);
    // 4. join
    cudaStreamWaitEvent(0, e2, 0);

    cudaEventDestroy(e1);
    cudaEventDestroy(e2);
    cudaStreamDestroy(s2);
}

// round 17
// speedup vs baseline: 2.4807x; 2.4807x over previous
#include <cuda_runtime.h>
#include <cuda_fp16.h>
#include <cuda_fp8.h>
#include <cstdint>

// Problem shapes (fixed by the dataset)
#define M_FULL  16384
#define N_DIM   4096
#define K_DIM   4096

// Scratch (allocation-free rule: __device__ globals)
__device__ __half g_A16[(size_t)(M_FULL / 2) * K_DIM];  // fp16 Asum [M][K]
__device__ __half g_B16[(size_t)K_DIM * N_DIM];          // fp16 B^T [N][K]

// ---------------------------------------------------------------------------
// fp8 helpers
// ---------------------------------------------------------------------------
__device__ __forceinline__ float fp8_round(float x) {
    __nv_fp8_storage_t s = __nv_cvt_float_to_fp8(x, __NV_SATFINITE, __NV_E4M3);
    __half_raw hr = __nv_cvt_fp8_to_halfraw(s, __NV_E4M3);
    return __half2float(__half(hr));
}
__device__ __forceinline__ __half fp8_to_half(float x) {
    __nv_fp8_storage_t s = __nv_cvt_float_to_fp8(x, __NV_SATFINITE, __NV_E4M3);
    __half_raw hr = __nv_cvt_fp8_to_halfraw(s, __NV_E4M3);  // e4m3 exact in fp16
    return __half(hr);
}
__device__ __forceinline__ float4 ldcs4(const float4* p) {
    float4 v;
    asm volatile("ld.global.cs.v4.f32 {%0,%1,%2,%3}, [%4];"
                 : "=f"(v.x), "=f"(v.y), "=f"(v.z), "=f"(v.w) : "l"(p));
    return v;
}

// ---------------------------------------------------------------------------
// Fused prep kernel:
//   part 1 (blocks [0, rblocks)): Asum = sum_w fp8round(A_w), fp32 acc -> fp16
//       2 float4 per thread (MLP 16), streaming loads (A is read-once).
//   part 2 (rest): W [K][N] f32 -> g_B16 = B^T [N][K] fp16
// ---------------------------------------------------------------------------
__global__ __launch_bounds__(256)
void prep_kernel(const float* __restrict__ A, const float* __restrict__ W,
                 int shard4, int world, int rblocks) {
    if ((int)blockIdx.x < rblocks) {
        int idx0 = blockIdx.x * 512 + threadIdx.x;      // 2 quads per thread
        const float4* A4 = (const float4*)A;
        float4 s0 = make_float4(0.f, 0.f, 0.f, 0.f);
        float4 s1 = make_float4(0.f, 0.f, 0.f, 0.f);
        int idx1 = idx0 + 256;
        bool v1 = idx1 < shard4;
        if (idx0 >= shard4) return;
        for (int w = 0; w < world; w++) {
            float4 a = ldcs4(&A4[(size_t)w * shard4 + idx0]);
            float4 b = v1 ? ldcs4(&A4[(size_t)w * shard4 + idx1])
                          : make_float4(0.f, 0.f, 0.f, 0.f);
            s0.x += fp8_round(a.x); s0.y += fp8_round(a.y);
            s0.z += fp8_round(a.z); s0.w += fp8_round(a.w);
            s1.x += fp8_round(b.x); s1.y += fp8_round(b.y);
            s1.z += fp8_round(b.z); s1.w += fp8_round(b.w);
        }
        ((__half2*)g_A16)[idx0 * 2 + 0] = __floats2half2_rn(s0.x, s0.y);
        ((__half2*)g_A16)[idx0 * 2 + 1] = __floats2half2_rn(s0.z, s0.w);
        if (v1) {
            ((__half2*)g_A16)[idx1 * 2 + 0] = __floats2half2_rn(s1.x, s1.y);
            ((__half2*)g_A16)[idx1 * 2 + 1] = __floats2half2_rn(s1.z, s1.w);
        }
    } else {
        __shared__ float t[32][33];
        int q = blockIdx.x - rblocks;              // 0 .. 128*128-1
        int n0 = (q & 127) * 32;
        int k0 = (q >> 7) * 32;
        int tx = threadIdx.x & 31, ty = threadIdx.x >> 5;   // (32, 8)
#pragma unroll
        for (int i = 0; i < 4; i++)
            t[ty + 8 * i][tx] = W[(size_t)(k0 + ty + 8 * i) * N_DIM + n0 + tx];
        __syncthreads();
#pragma unroll
        for (int i = 0; i < 4; i++)
            g_B16[(size_t)(n0 + ty + 8 * i) * K_DIM + k0 + tx] = fp8_to_half(t[tx][ty + 8 * i]);
    }
}

// ---------------------------------------------------------------------------
// PTX helpers (sm_80-era instructions; valid on compute_103)
// ---------------------------------------------------------------------------
__device__ __forceinline__ uint32_t smem_u32(const void* p) {
    uint32_t a;
    asm("{ .reg .u64 t; cvta.to.shared.u64 t, %1; cvt.u32.u64 %0, t; }" : "=r"(a) : "l"(p));
    return a;
}
__device__ __forceinline__ void ldsm_x4(uint32_t& r0, uint32_t& r1, uint32_t& r2, uint32_t& r3,
                                        uint32_t addr) {
    asm volatile("ldmatrix.sync.aligned.m8n8.x4.shared.b16 {%0,%1,%2,%3}, [%4];"
                 : "=r"(r0), "=r"(r1), "=r"(r2), "=r"(r3) : "r"(addr));
}
__device__ __forceinline__ void mma_16816(float* c, const uint32_t* a, uint32_t b0, uint32_t b1) {
    asm volatile("mma.sync.aligned.m16n8k16.row.col.f32.f16.f16.f32 "
                 "{%0,%1,%2,%3}, {%4,%5,%6,%7}, {%8,%9}, {%0,%1,%2,%3};"
                 : "+f"(c[0]), "+f"(c[1]), "+f"(c[2]), "+f"(c[3])
                 : "r"(a[0]), "r"(a[1]), "r"(a[2]), "r"(a[3]), "r"(b0), "r"(b1));
}
__device__ __forceinline__ void cp16(uint32_t smem, const void* g) {
    asm volatile("cp.async.cg.shared.global [%0], [%1], 16;" :: "r"(smem), "l"(g) : "memory");
}
#define CP_COMMIT() asm volatile("cp.async.commit_group;" ::: "memory")
#define CP_WAIT(n)  asm volatile("cp.async.wait_group %0;" :: "n"(n) : "memory")

// ---------------------------------------------------------------------------
// GEMM (R12-proven best, byte-identical): 128x256 CTA tile, 8 warps (64x64
// warp tile), BK=64, 4-stage cp.async ring, reg double-buffered fragments,
// cp.async spread across ks-steps, fused scale_b + fp16 epilogue.
// ---------------------------------------------------------------------------
#define BM 128
#define BN 256
#define BKH 64
#define STAGES 4
#define ROWB 128
#define A_STAGE (BM * ROWB)           // 16 KB
#define B_STAGE (BN * ROWB)           // 32 KB
#define STAGE_BYTES (A_STAGE + B_STAGE)
#define GEMM_SMEM (STAGES * STAGE_BYTES)   // 192 KB, 1 CTA/SM

__device__ __forceinline__ uint32_t sw_off(int row, int chunk) {
    return (uint32_t)(row * ROWB + ((chunk ^ (row & 7)) << 4));
}

__global__ __launch_bounds__(256, 1)
void gemm_mma_kernel(const float* __restrict__ scale_b, float* __restrict__ out) {
    extern __shared__ char sm[];
    const uint32_t sbase = smem_u32(sm);

    const int tid  = threadIdx.x;
    const int lane = tid & 31;
    const int warp = tid >> 5;        // 0..7
    const int wm   = warp & 1;        // 0..1 -> 64-row group
    const int wn   = warp >> 1;       // 0..3 -> 64-col group
    const int bm = blockIdx.y * BM;
    const int bn = blockIdx.x * BN;

    const __half* Ag = g_A16 + (size_t)bm * K_DIM;
    const __half* Bg = g_B16 + (size_t)bn * K_DIM;

    const int crow = tid >> 3;
    const int cchk = tid & 7;

    float acc[4][8][4] = {};          // [mi][n8][reg] -> 128 regs

    const int KITER = K_DIM / BKH;    // 64
    const int arow = wm * 64 + (lane & 15);
    const int brow = wn * 64 + (lane & 15);
    const int chsel = lane >> 4;

    // Prologue: fill stages 0..STAGES-2
#pragma unroll
    for (int s = 0; s < STAGES - 1; s++) {
        const __half* ga = Ag + (size_t)s * BKH + cchk * 8;
        const __half* gb = Bg + (size_t)s * BKH + cchk * 8;
        uint32_t as = sbase + s * STAGE_BYTES;
        uint32_t bs = as + A_STAGE;
#pragma unroll
        for (int i = 0; i < 4; i++)
            cp16(as + sw_off(crow + i * 32, cchk), ga + (size_t)(crow + i * 32) * K_DIM);
#pragma unroll
        for (int i = 0; i < 8; i++)
            cp16(bs + sw_off(crow + i * 32, cchk), gb + (size_t)(crow + i * 32) * K_DIM);
        CP_COMMIT();
    }

    uint32_t af[2][4][4];             // [buf][mi][reg]
    uint32_t bf[2][4][4];             // [buf][nj][reg]

    for (int it = 0; it < KITER; it++) {
        CP_WAIT(STAGES - 2);
        __syncthreads();              // stage it ready; refill target stage free

        const uint32_t As = sbase + (it % STAGES) * STAGE_BYTES;
        const uint32_t Bs = As + A_STAGE;

        const int nk = it + STAGES - 1;
        const bool do_ld = (nk < KITER);
        const __half* ga = Ag + (size_t)nk * BKH + cchk * 8;
        const __half* gb = Bg + (size_t)nk * BKH + cchk * 8;
        const uint32_t nas = sbase + (nk % STAGES) * STAGE_BYTES;
        const uint32_t nbs = nas + A_STAGE;

        // Preload ks=0 fragments into buffer 0
        {
            const int ch = chsel;
#pragma unroll
            for (int mi = 0; mi < 4; mi++)
                ldsm_x4(af[0][mi][0], af[0][mi][1], af[0][mi][2], af[0][mi][3],
                        As + sw_off(arow + mi * 16, ch));
#pragma unroll
            for (int nj = 0; nj < 4; nj++)
                ldsm_x4(bf[0][nj][0], bf[0][nj][1], bf[0][nj][2], bf[0][nj][3],
                        Bs + sw_off(brow + nj * 16, ch));
        }

#pragma unroll
        for (int ks = 0; ks < 4; ks++) {
            const int cur = ks & 1;
            const int nxt = cur ^ 1;

            if (ks < 3) {
                const int ch = (ks + 1) * 2 + chsel;
#pragma unroll
                for (int mi = 0; mi < 4; mi++)
                    ldsm_x4(af[nxt][mi][0], af[nxt][mi][1], af[nxt][mi][2], af[nxt][mi][3],
                            As + sw_off(arow + mi * 16, ch));
#pragma unroll
                for (int nj = 0; nj < 4; nj++)
                    ldsm_x4(bf[nxt][nj][0], bf[nxt][nj][1], bf[nxt][nj][2], bf[nxt][nj][3],
                            Bs + sw_off(brow + nj * 16, ch));
            }

            if (do_ld) {
                int r = crow + ks * 32;
                cp16(nas + sw_off(r, cchk), ga + (size_t)r * K_DIM);
                int r0 = crow + (ks * 2) * 32;
                int r1 = crow + (ks * 2 + 1) * 32;
                cp16(nbs + sw_off(r0, cchk), gb + (size_t)r0 * K_DIM);
                cp16(nbs + sw_off(r1, cchk), gb + (size_t)r1 * K_DIM);
            }
            if (ks == 3) CP_COMMIT();

#pragma unroll
            for (int mi = 0; mi < 4; mi++)
#pragma unroll
                for (int n8 = 0; n8 < 8; n8++) {
                    int nj = n8 >> 1, hi = n8 & 1;
                    mma_16816(acc[mi][n8], af[cur][mi], bf[cur][nj][hi], bf[cur][nj][hi + 2]);
                }
        }
    }

    // Fused epilogue: scale_b + fp16 quantize, store fp32
#pragma unroll
    for (int mi = 0; mi < 4; mi++) {
#pragma unroll
        for (int n8 = 0; n8 < 8; n8++) {
            const float* c = acc[mi][n8];
            int row = bm + wm * 64 + mi * 16 + (lane >> 2);
            int col = bn + wn * 64 + n8 * 8 + (lane & 3) * 2;
            float2 s0 = *(const float2*)&scale_b[col];
            float2 v0;
            v0.x = __half2float(__float2half(c[0] * s0.x));
            v0.y = __half2float(__float2half(c[1] * s0.y));
            *(float2*)&out[(size_t)row * N_DIM + col] = v0;
            float2 v1;
            v1.x = __half2float(__float2half(c[2] * s0.x));
            v1.y = __half2float(__float2half(c[3] * s0.y));
            *(float2*)&out[(size_t)(row + 8) * N_DIM + col] = v1;
        }
    }
}

// ---------------------------------------------------------------------------
// Host
// ---------------------------------------------------------------------------
extern "C" void kernel_launch(void* const* d_in, const int* in_sizes, int n_in,
                              void* d_out, int out_size) {
    const float* input = nullptr; const float* weight = nullptr; const float* scale_b = nullptr;
    long long input_elems = 0;
    for (int i = 0; i < n_in; i++) {
        long long sz = in_sizes[i];
        if (sz == (long long)K_DIM * N_DIM && !weight)      weight = (const float*)d_in[i];
        else if (sz == N_DIM && !scale_b)                   scale_b = (const float*)d_in[i];
        else if (sz > (long long)K_DIM * N_DIM)             { input = (const float*)d_in[i]; input_elems = sz; }
    }
    float* out = (float*)d_out;   // harness output buffer is FLOAT32

    long long M_full   = input_elems / K_DIM;
    long long out_rows = (long long)out_size / N_DIM;
    int world = (int)(M_full / (out_rows > 0 ? out_rows : M_full));
    if (world < 1) world = 1;
    int M_out = (int)(M_full / world);

    {
        int shard4 = (M_out * K_DIM) / 4;
        int rblocks = (shard4 + 511) / 512;      // 2 quads per thread
        int tblocks = (N_DIM / 32) * (K_DIM / 32);
        prep_kernel<<<rblocks + tblocks, 256>>>(input, weight, shard4, world, rblocks);
    }
    {
        cudaFuncSetAttribute(gemm_mma_kernel, cudaFuncAttributeMaxDynamicSharedMemorySize,
                             GEMM_SMEM);
        dim3 grid(N_DIM / BN, M_out / BM);
        gemm_mma_kernel<<<grid, 256, GEMM_SMEM>>>(scale_b, out);
    }
}